// round 14
// baseline (speedup 1.0000x reference)
#include <cuda_runtime.h>
#include <cuda_fp16.h>
#include <cuda_bf16.h>
#include <mma.h>
#include <cstddef>
#include <cstdint>
#include <math.h>

using namespace nvcuda;

// Problem constants
#define BB 8
#define CC 256
#define HH 128
#define WW2 128
#define NN 16384           // H*W
#define BN 131072          // B*N
#define QKVC 768           // 3C
#define HC 512             // 2C
#define OSTR 2560          // fused GEMM output columns

// column offsets inside the fused output  [gqkv 0..768 | gh 768..1280 | wqkv 1280..2048 | wh 2048..2560]
#define OFF_GQKV 0
#define OFF_GH   768
#define OFF_WQKV 1280
#define OFF_WH   2048

// ---------------- scratch (device globals; no allocation) ----------------
__device__ __half d_big[(size_t)BN * OSTR];  // fused GEMM output, fp16 (670 MB)
__device__ __half d_xh[(size_t)BB * CC * NN];
__device__ __half d_wh[(size_t)CC * OSTR];
__device__ float d_xbit_g[BN];
__device__ float d_xbit_w[BN];
__device__ float d_mu[2][BB * HC];
__device__ float d_rstd[2][BB * HC];
__device__ float d_fw[2][HC];
__device__ float d_fb[2];

// ======================= helpers ============================
__device__ __forceinline__ uint32_t smem_u32(const void* p) {
    uint32_t a;
    asm("{ .reg .u64 t; cvta.to.shared.u64 t, %1; cvt.u32.u64 %0, t; }"
        : "=r"(a) : "l"(p));
    return a;
}
__device__ __forceinline__ void cp16(uint32_t dst, const void* src) {
    asm volatile("cp.async.cg.shared.global [%0], [%1], 16;"
                 :: "r"(dst), "l"(src));
}

// ================== convert x -> fp16, same layout ==================
__global__ __launch_bounds__(256) void split_x(const float* __restrict__ x)
{
    size_t i = ((size_t)blockIdx.x * 256 + threadIdx.x) * 4;
    float4 v = *(const float4*)&x[i];
    __half h[4];
    h[0] = __float2half_rn(v.x);
    h[1] = __float2half_rn(v.y);
    h[2] = __float2half_rn(v.z);
    h[3] = __float2half_rn(v.w);
    *(uint2*)&d_xh[i] = *(uint2*)h;
}

// ====== pack weights into [c][2560] fp16 (fused column space) ========
__global__ __launch_bounds__(256) void pack_w(
    const float* __restrict__ gq, const float* __restrict__ gf,
    const float* __restrict__ wq, const float* __restrict__ wf)
{
    int idx = blockIdx.x * 256 + threadIdx.x;   // 0 .. CC*OSTR-1
    int c = idx / OSTR;
    int j = idx % OSTR;
    const float* src; int jj; int ncol;
    if (j < 768)       { src = gq; jj = j;        ncol = QKVC; }
    else if (j < 1280) { src = gf; jj = j - 768;  ncol = HC;   }
    else if (j < 2048) { src = wq; jj = j - 1280; ncol = QKVC; }
    else               { src = wf; jj = j - 2048; ncol = HC;   }
    d_wh[idx] = __float2half_rn(src[(size_t)c * ncol + jj]);
}

// ====== WMMA fp16 GEMM: d_big = A @ W (f16-accum MMA, f32 merge) ==========
// Per kt (K=32): accumulate into fresh f16 fragments (2x tensor rate),
// then merge into persistent f32 fragments. f16/f32 accumulator fragment
// layouts verified identical (R12 vs R13 bit-identical rel_err).
#define BKT 32
#define LDAs 136
#define LDBs 264
#define ASTG (BKT * LDAs)
#define BSTG (BKT * LDBs)
#define STGE (ASTG + BSTG)
#define NSTG 4
#define GEMM_SMEM (NSTG * STGE * 2)

__global__ __launch_bounds__(512, 1) void gemm_f16()
{
    extern __shared__ __half sm[];
    const uint32_t smb = smem_u32(sm);
    const int t   = threadIdx.x;
    const int wid = t >> 5;

    const int nt = blockIdx.x;
    const int mt = blockIdx.y;
    const int j0 = nt * 256;
    const int r0 = mt * 128;
    const int b  = mt >> 7;
    const int n0 = r0 & (NN - 1);

    const __half* ax = d_xh + (size_t)b * CC * NN + n0;
    const __half* bw = d_wh + j0;

    const int wm = (wid & 3) * 32;
    const int wn = (wid >> 2) * 64;

    wmma::fragment<wmma::accumulator, 16, 16, 16, float> acc[2][4];
#pragma unroll
    for (int i = 0; i < 2; i++)
#pragma unroll
        for (int j = 0; j < 4; j++) wmma::fill_fragment(acc[i][j], 0.0f);

    auto load_stage = [&](int s, int c0) {
        const uint32_t sbase = smb + (uint32_t)(s * STGE) * 2;
#pragma unroll
        for (int i = 0; i < 3; i++) {
            int q = t + i * 512;
            if (q < 512) {
                int k = q >> 4, c8 = (q & 15) << 3;
                cp16(sbase + (uint32_t)(k * LDAs + c8) * 2,
                     ax + (size_t)(c0 + k) * NN + c8);
            } else {
                int q2 = q - 512;
                int k = q2 >> 5, j8 = (q2 & 31) << 3;
                cp16(sbase + (uint32_t)(ASTG + k * LDBs + j8) * 2,
                     bw + (size_t)(c0 + k) * OSTR + j8);
            }
        }
        asm volatile("cp.async.commit_group;");
    };

    load_stage(0, 0);
    load_stage(1, BKT);
    load_stage(2, 2 * BKT);

#pragma unroll 1
    for (int kt = 0; kt < 8; kt++) {
        if (kt + 3 < 8) {
            load_stage((kt + 3) & 3, (kt + 3) * BKT);
            asm volatile("cp.async.wait_group 3;");
        } else if (kt + 2 < 8) {
            asm volatile("cp.async.wait_group 2;");
        } else if (kt + 1 < 8) {
            asm volatile("cp.async.wait_group 1;");
        } else {
            asm volatile("cp.async.wait_group 0;");
        }
        __syncthreads();

        const __half* st = sm + (size_t)(kt & 3) * STGE;
        const __half* As = st;
        const __half* Bs = st + ASTG;

        // fresh f16 accumulators for this K=32 window
        wmma::fragment<wmma::accumulator, 16, 16, 16, __half> hacc[2][4];
#pragma unroll
        for (int i = 0; i < 2; i++)
#pragma unroll
            for (int j = 0; j < 4; j++)
                wmma::fill_fragment(hacc[i][j], __float2half(0.0f));

#pragma unroll
        for (int ks = 0; ks < 2; ks++) {
            wmma::fragment<wmma::matrix_a, 16, 16, 16, __half,
                           wmma::col_major> af[2];
            wmma::load_matrix_sync(af[0], As + (ks * 16) * LDAs + wm, LDAs);
            wmma::load_matrix_sync(af[1], As + (ks * 16) * LDAs + wm + 16, LDAs);
#pragma unroll
            for (int j = 0; j < 4; j++) {
                wmma::fragment<wmma::matrix_b, 16, 16, 16, __half,
                               wmma::row_major> bf;
                wmma::load_matrix_sync(bf, Bs + (ks * 16) * LDBs + wn + j * 16, LDBs);
                wmma::mma_sync(hacc[0][j], af[0], bf, hacc[0][j]);
                wmma::mma_sync(hacc[1][j], af[1], bf, hacc[1][j]);
            }
        }

        // merge f16 window into f32 accumulators (packed half2 converts)
#pragma unroll
        for (int i = 0; i < 2; i++)
#pragma unroll
            for (int j = 0; j < 4; j++) {
#pragma unroll
                for (int e = 0; e < 8; e += 2) {
                    float2 f = __half22float2(*(__half2*)&hacc[i][j].x[e]);
                    acc[i][j].x[e]     += f.x;
                    acc[i][j].x[e + 1] += f.y;
                }
            }
        __syncthreads();
    }

    // epilogue: convert f32 accum -> f16 accum fragment, direct store
#pragma unroll
    for (int i = 0; i < 2; i++)
#pragma unroll
        for (int j = 0; j < 4; j++) {
            wmma::fragment<wmma::accumulator, 16, 16, 16, __half> ho;
#pragma unroll
            for (int e = 0; e < ho.num_elements; e++)
                ho.x[e] = __float2half_rn(acc[i][j].x[e]);
            wmma::store_matrix_sync(
                d_big + (size_t)(r0 + wm + i * 16) * OSTR + j0 + wn + j * 16,
                ho, OSTR, wmma::mem_row_major);
        }
}

// ======== fused tensor-core attention (both branches) + final blend ========
#define LDH 72
#define LDS4 68
#define A_QH   0
#define A_KH   9216
#define A_VH   18432
#define A_PH   27648
#define A_SS   36864
#define A_CG   54272
#define A_BG   71680
#define A_BW   71936
#define ATTN_SMEM 72192

__global__ __launch_bounds__(256) void attn_combine(
    const float* __restrict__ x, float* __restrict__ out)
{
    extern __shared__ char smem[];
    __half* Qh = (__half*)(smem + A_QH);
    __half* Kh = (__half*)(smem + A_KH);
    __half* Vh = (__half*)(smem + A_VH);
    __half* Ph = (__half*)(smem + A_PH);
    float*  Ss = (float*)(smem + A_SS);
    float*  Cg = (float*)(smem + A_CG);
    float*  sbg = (float*)(smem + A_BG);
    float*  sbw = (float*)(smem + A_BW);

    const int t    = threadIdx.x;
    const int wid  = t >> 5;
    const int bx   = blockIdx.x;
    const int win  = bx >> 2;
    const int head = bx & 3;
    const int b    = win >> 8;
    const int wib  = win & 255;
    const int xw   = wib >> 4;
    const int yw   = wib & 15;

    const int li  = t >> 2;            // token 0..63
    const int ld0 = (t & 3) << 4;      // 16 d's per thread
    const int lni = ((xw << 3) + (li >> 3)) * WW2 + (yw << 3) + (li & 7);

    if (t < 64) {
        int ni = ((xw << 3) + (t >> 3)) * WW2 + (yw << 3) + (t & 7);
        sbg[t] = d_xbit_g[(size_t)b * NN + ni];
    } else if (t < 128) {
        int tt = t - 64;
        int ni = ((xw << 3) + (tt >> 3)) * WW2 + (yw << 3) + (tt & 7);
        sbw[tt] = d_xbit_w[(size_t)b * NN + ni];
    }

    const int wi = (wid >> 1) * 16;
    const int wj = (wid & 1) * 32;
    const __half2 qscale = __half2half2(__float2half_rn(0.125f));

#pragma unroll
    for (int br = 0; br < 2; br++) {
        const int qoff = (br ? OFF_WQKV : OFF_GQKV) + head * 64;
        float* cdst = br ? Ss : Cg;

        // ---- load QKV (fp16 global -> fp16 smem) ----
        {
            const __half* rp = d_big + (size_t)(b * NN + lni) * OSTR + qoff;
#pragma unroll
            for (int u = 0; u < 2; u++) {
                int d = ld0 + u * 8;
                uint4 qv = *(const uint4*)&rp[d];
                __half2* q2 = (__half2*)&qv;
                q2[0] = __hmul2(q2[0], qscale);
                q2[1] = __hmul2(q2[1], qscale);
                q2[2] = __hmul2(q2[2], qscale);
                q2[3] = __hmul2(q2[3], qscale);
                *(uint4*)&Qh[li * LDH + d] = qv;
                *(uint4*)&Kh[li * LDH + d] = *(const uint4*)&rp[256 + d];
                *(uint4*)&Vh[li * LDH + d] = *(const uint4*)&rp[512 + d];
            }
        }
        __syncthreads();

        // ---- S = Q K^T ----
        {
            wmma::fragment<wmma::accumulator, 16, 16, 16, float> c0, c1;
            wmma::fill_fragment(c0, 0.0f);
            wmma::fill_fragment(c1, 0.0f);
#pragma unroll
            for (int k0 = 0; k0 < 64; k0 += 16) {
                wmma::fragment<wmma::matrix_a, 16, 16, 16, __half,
                               wmma::row_major> af;
                wmma::fragment<wmma::matrix_b, 16, 16, 16, __half,
                               wmma::col_major> bf0, bf1;
                wmma::load_matrix_sync(af,  Qh + wi * LDH + k0, LDH);
                wmma::load_matrix_sync(bf0, Kh + wj * LDH + k0, LDH);
                wmma::load_matrix_sync(bf1, Kh + (wj + 16) * LDH + k0, LDH);
                wmma::mma_sync(c0, af, bf0, c0);
                wmma::mma_sync(c1, af, bf1, c1);
            }
            wmma::store_matrix_sync(Ss + wi * LDS4 + wj,      c0, LDS4,
                                    wmma::mem_row_major);
            wmma::store_matrix_sync(Ss + wi * LDS4 + wj + 16, c1, LDS4,
                                    wmma::mem_row_major);
        }
        __syncthreads();

        // ---- softmax: 4 lanes per row ----
        {
            const int row = t >> 2;
            const int qq  = t & 3;
            float* sr = Ss + row * LDS4 + qq * 16;
            float4 v0 = *(float4*)&sr[0];
            float4 v1 = *(float4*)&sr[4];
            float4 v2 = *(float4*)&sr[8];
            float4 v3 = *(float4*)&sr[12];
            float m = fmaxf(fmaxf(fmaxf(v0.x, v0.y), fmaxf(v0.z, v0.w)),
                     fmaxf(fmaxf(fmaxf(v1.x, v1.y), fmaxf(v1.z, v1.w)),
                     fmaxf(fmaxf(fmaxf(v2.x, v2.y), fmaxf(v2.z, v2.w)),
                           fmaxf(fmaxf(v3.x, v3.y), fmaxf(v3.z, v3.w)))));
            m = fmaxf(m, __shfl_xor_sync(0xffffffffu, m, 1));
            m = fmaxf(m, __shfl_xor_sync(0xffffffffu, m, 2));
            float e[16];
            e[0] = __expf(v0.x - m); e[1] = __expf(v0.y - m);
            e[2] = __expf(v0.z - m); e[3] = __expf(v0.w - m);
            e[4] = __expf(v1.x - m); e[5] = __expf(v1.y - m);
            e[6] = __expf(v1.z - m); e[7] = __expf(v1.w - m);
            e[8] = __expf(v2.x - m); e[9] = __expf(v2.y - m);
            e[10] = __expf(v2.z - m); e[11] = __expf(v2.w - m);
            e[12] = __expf(v3.x - m); e[13] = __expf(v3.y - m);
            e[14] = __expf(v3.z - m); e[15] = __expf(v3.w - m);
            float sum = 0.f;
#pragma unroll
            for (int u = 0; u < 16; u++) sum += e[u];
            sum += __shfl_xor_sync(0xffffffffu, sum, 1);
            sum += __shfl_xor_sync(0xffffffffu, sum, 2);
            float inv = 1.0f / sum;
            __half* pr = Ph + row * LDH + qq * 16;
#pragma unroll
            for (int u = 0; u < 4; u++) {
                __half hp[4] = {
                    __float2half_rn(e[u * 4 + 0] * inv),
                    __float2half_rn(e[u * 4 + 1] * inv),
                    __float2half_rn(e[u * 4 + 2] * inv),
                    __float2half_rn(e[u * 4 + 3] * inv)};
                *(uint2*)&pr[u * 4] = *(uint2*)hp;
            }
        }
        __syncthreads();

        // ---- ctx = P V ----
        {
            wmma::fragment<wmma::accumulator, 16, 16, 16, float> c0, c1;
            wmma::fill_fragment(c0, 0.0f);
            wmma::fill_fragment(c1, 0.0f);
#pragma unroll
            for (int k0 = 0; k0 < 64; k0 += 16) {
                wmma::fragment<wmma::matrix_a, 16, 16, 16, __half,
                               wmma::row_major> af;
                wmma::fragment<wmma::matrix_b, 16, 16, 16, __half,
                               wmma::row_major> bf0, bf1;
                wmma::load_matrix_sync(af,  Ph + wi * LDH + k0, LDH);
                wmma::load_matrix_sync(bf0, Vh + k0 * LDH + wj, LDH);
                wmma::load_matrix_sync(bf1, Vh + k0 * LDH + wj + 16, LDH);
                wmma::mma_sync(c0, af, bf0, c0);
                wmma::mma_sync(c1, af, bf1, c1);
            }
            wmma::store_matrix_sync(cdst + wi * LDS4 + wj,      c0, LDS4,
                                    wmma::mem_row_major);
            wmma::store_matrix_sync(cdst + wi * LDS4 + wj + 16, c1, LDS4,
                                    wmma::mem_row_major);
        }
        __syncthreads();
    }

    // ---- final blend ----
    for (int e = t; e < 4096; e += 256) {
        int d  = e >> 6;
        int ii = e & 63;
        int ni = ((xw << 3) + (ii >> 3)) * WW2 + (yw << 3) + (ii & 7);
        size_t gidx = ((size_t)(b * CC + head * 64 + d)) * NN + ni;
        float vg = Cg[ii * LDS4 + d];
        float vw = Ss[ii * LDS4 + d];
        float wv = sbw[ii] * vw;
        float sg = 1.0f / (1.0f + __expf(-wv));
        out[gidx] = x[gidx] * sg + (sbg[ii] * vg) * (1.0f - sg);
    }
}

// --------- fold fc2+bit into a single 2C vector (warp per k) --------------
__global__ __launch_bounds__(256) void fuse_fw(
    const float* __restrict__ gfc2w, const float* __restrict__ gfc2b,
    const float* __restrict__ gbitw, const float* __restrict__ gbitb,
    const float* __restrict__ wfc2w, const float* __restrict__ wfc2b,
    const float* __restrict__ wbitw, const float* __restrict__ wbitb)
{
    const int sel  = blockIdx.y;
    const float* fc2w = sel ? wfc2w : gfc2w;
    const float* fc2b = sel ? wfc2b : gfc2b;
    const float* bitw = sel ? wbitw : gbitw;
    const float* bitb = sel ? wbitb : gbitb;

    const int wid  = threadIdx.x >> 5;
    const int lane = threadIdx.x & 31;
    const int k    = blockIdx.x * 8 + wid;

    float s = 0.f;
#pragma unroll
    for (int c = lane; c < CC; c += 32)
        s += fc2w[(size_t)k * CC + c] * bitw[c];
#pragma unroll
    for (int off = 16; off > 0; off >>= 1)
        s += __shfl_xor_sync(0xffffffffu, s, off);
    if (lane == 0) d_fw[sel][k] = s;

    if (blockIdx.x == 0 && wid == 0) {
        float sb = 0.f;
#pragma unroll
        for (int c = lane; c < CC; c += 32)
            sb += fc2b[c] * bitw[c];
#pragma unroll
        for (int off = 16; off > 0; off >>= 1)
            sb += __shfl_xor_sync(0xffffffffu, sb, off);
        if (lane == 0) d_fb[sel] = sb + bitb[0];
    }
}

// -------- InstanceNorm stats, vectorized: thread reads 8 halves/row --------
__global__ __launch_bounds__(256) void inorm_stats()
{
    const int b   = blockIdx.x;
    const int sel = blockIdx.y;
    const int ch0 = blockIdx.z * 256;
    const int hoff = (sel ? OFF_WH : OFF_GH) + ch0;
    const int g  = threadIdx.x & 31;    // 8-channel group
    const int rr = threadIdx.x >> 5;    // row lane

    float s[8], s2[8];
#pragma unroll
    for (int u = 0; u < 8; u++) { s[u] = 0.f; s2[u] = 0.f; }

    const __half* base = d_big + (size_t)b * NN * OSTR + hoff + g * 8;
    for (int n = rr; n < NN; n += 8) {
        uint4 pk = *(const uint4*)&base[(size_t)n * OSTR];
        __half2* h2 = (__half2*)&pk;
#pragma unroll
        for (int u = 0; u < 4; u++) {
            float2 f = __half22float2(h2[u]);
            s[2 * u]      += f.x; s2[2 * u]      += f.x * f.x;
            s[2 * u + 1]  += f.y; s2[2 * u + 1]  += f.y * f.y;
        }
    }

    __shared__ float ss[8][256], ss2[8][256];
#pragma unroll
    for (int u = 0; u < 8; u++) {
        ss[rr][g * 8 + u]  = s[u];
        ss2[rr][g * 8 + u] = s2[u];
    }
    __syncthreads();

    const int c = threadIdx.x;
    float a = 0.f, a2 = 0.f;
#pragma unroll
    for (int r = 0; r < 8; r++) { a += ss[r][c]; a2 += ss2[r][c]; }
    float m   = a * (1.0f / NN);
    float var = a2 * (1.0f / NN) - m * m;
    d_mu[sel][b * HC + ch0 + c]   = m;
    d_rstd[sel][b * HC + ch0 + c] = rsqrtf(var + 1e-5f);
}

// ---------------- norm + gelu + fused fc2/bit GEMV -> x_bit ----------------
__global__ __launch_bounds__(256) void mlp_bit()
{
    const int sel  = blockIdx.y;
    const int hoff = sel ? OFF_WH : OFF_GH;
    float* xbit    = sel ? d_xbit_w : d_xbit_g;

    __shared__ float smu[HC], srs[HC], sfw[HC];
    const int t  = threadIdx.x;
    const int r0 = blockIdx.x * 8;
    const int b  = r0 >> 14;

    smu[t]       = d_mu[sel][b * HC + t];
    smu[t + 256] = d_mu[sel][b * HC + t + 256];
    srs[t]       = d_rstd[sel][b * HC + t];
    srs[t + 256] = d_rstd[sel][b * HC + t + 256];
    sfw[t]       = d_fw[sel][t];
    sfw[t + 256] = d_fw[sel][t + 256];
    __syncthreads();

    const float fb = d_fb[sel];
    const int w = t >> 5, lane = t & 31;
    const int r = r0 + w;
    const __half* hr = d_big + (size_t)r * OSTR + hoff;

    float acc = 0.f;
#pragma unroll
    for (int ii = 0; ii < 8; ii++) {
        int k = (lane + (ii << 5)) * 2;
        __half2 hv = *(const __half2*)&hr[k];
        float2 vf = __half22float2(hv);
        float v0 = (vf.x - smu[k]) * srs[k];
        float v1 = (vf.y - smu[k + 1]) * srs[k + 1];
        float g0 = 0.5f * v0 * (1.0f + erff(v0 * 0.70710678118f));
        float g1 = 0.5f * v1 * (1.0f + erff(v1 * 0.70710678118f));
        acc += g0 * sfw[k] + g1 * sfw[k + 1];
    }
#pragma unroll
    for (int off = 16; off > 0; off >>= 1)
        acc += __shfl_xor_sync(0xffffffffu, acc, off);
    if (lane == 0) xbit[r] = fmaxf(acc + fb, 0.0f);
}

// ---------------- launch ----------------
extern "C" void kernel_launch(void* const* d_in, const int* in_sizes, int n_in,
                              void* d_out, int out_size)
{
    const float* x       = (const float*)d_in[0];
    const float* g_qkv   = (const float*)d_in[1];
    const float* g_fc1_w = (const float*)d_in[2];
    const float* g_fc2_w = (const float*)d_in[4];
    const float* g_fc2_b = (const float*)d_in[5];
    const float* g_bit_w = (const float*)d_in[6];
    const float* g_bit_b = (const float*)d_in[7];
    const float* w_qkv   = (const float*)d_in[8];
    const float* w_fc1_w = (const float*)d_in[9];
    const float* w_fc2_w = (const float*)d_in[11];
    const float* w_fc2_b = (const float*)d_in[12];
    const float* w_bit_w = (const float*)d_in[13];
    const float* w_bit_b = (const float*)d_in[14];
    float* out = (float*)d_out;

    cudaFuncSetAttribute(gemm_f16, cudaFuncAttributeMaxDynamicSharedMemorySize,
                         GEMM_SMEM);
    cudaFuncSetAttribute(attn_combine, cudaFuncAttributeMaxDynamicSharedMemorySize,
                         ATTN_SMEM);

    // prep (fuse_fw is input-only -> moved before gemm so gemm is launch #4,
    // which is the launch the ncu capture window lands on)
    split_x<<<((size_t)BB * CC * NN / 4) / 256, 256>>>(x);
    pack_w<<<(CC * OSTR) / 256, 256>>>(g_qkv, g_fc1_w, w_qkv, w_fc1_w);
    fuse_fw<<<dim3(HC / 8, 2), 256>>>(g_fc2_w, g_fc2_b, g_bit_w, g_bit_b,
                                      w_fc2_w, w_fc2_b, w_bit_w, w_bit_b);

    // one fused tensor-core GEMM (f16-accum MMA + f32 merge): [BN,256]@[256,2560]
    gemm_f16<<<dim3(OSTR / 256, BN / 128), 512, GEMM_SMEM>>>();

    // bit branch (attn_combine consumes x_bit)
    inorm_stats<<<dim3(BB, 2, 2), 256>>>();
    mlp_bit<<<dim3(BN / 8, 2), 256>>>();

    // fused tensor-core attention (both branches) + final blend
    attn_combine<<<8192, 256, ATTN_SMEM>>>(x, out);
}

// round 16
// speedup vs baseline: 1.1467x; 1.1467x over previous
#include <cuda_runtime.h>
#include <cuda_fp16.h>
#include <cuda_bf16.h>
#include <mma.h>
#include <cstddef>
#include <cstdint>
#include <math.h>

using namespace nvcuda;

// Problem constants
#define BB 8
#define CC 256
#define HH 128
#define WW2 128
#define NN 16384           // H*W
#define BN 131072          // B*N
#define QKVC 768           // 3C
#define HC 512             // 2C
#define OSTR 2560          // fused GEMM output columns

// column offsets inside the fused output  [gqkv 0..768 | gh 768..1280 | wqkv 1280..2048 | wh 2048..2560]
#define OFF_GQKV 0
#define OFF_GH   768
#define OFF_WQKV 1280
#define OFF_WH   2048

// ---------------- scratch (device globals; no allocation) ----------------
__device__ __half d_big[(size_t)BN * OSTR];  // fused GEMM output, fp16 (670 MB)
__device__ __half d_xh[(size_t)BB * CC * NN];
__device__ __half d_wh[(size_t)CC * OSTR];
__device__ float d_xbit_g[BN];
__device__ float d_xbit_w[BN];
__device__ float d_mu[2][BB * HC];
__device__ float d_rstd[2][BB * HC];
__device__ float d_fw[2][HC];
__device__ float d_fb[2];

// ======================= helpers ============================
__device__ __forceinline__ uint32_t smem_u32(const void* p) {
    uint32_t a;
    asm("{ .reg .u64 t; cvta.to.shared.u64 t, %1; cvt.u32.u64 %0, t; }"
        : "=r"(a) : "l"(p));
    return a;
}
__device__ __forceinline__ void cp16(uint32_t dst, const void* src) {
    asm volatile("cp.async.cg.shared.global [%0], [%1], 16;"
                 :: "r"(dst), "l"(src));
}

// ================== convert x -> fp16, same layout ==================
__global__ __launch_bounds__(256) void split_x(const float* __restrict__ x)
{
    size_t i = ((size_t)blockIdx.x * 256 + threadIdx.x) * 4;
    float4 v = *(const float4*)&x[i];
    __half h[4];
    h[0] = __float2half_rn(v.x);
    h[1] = __float2half_rn(v.y);
    h[2] = __float2half_rn(v.z);
    h[3] = __float2half_rn(v.w);
    *(uint2*)&d_xh[i] = *(uint2*)h;
}

// ====== pack weights into [c][2560] fp16 (fused column space) ========
__global__ __launch_bounds__(256) void pack_w(
    const float* __restrict__ gq, const float* __restrict__ gf,
    const float* __restrict__ wq, const float* __restrict__ wf)
{
    int idx = blockIdx.x * 256 + threadIdx.x;   // 0 .. CC*OSTR-1
    int c = idx / OSTR;
    int j = idx % OSTR;
    const float* src; int jj; int ncol;
    if (j < 768)       { src = gq; jj = j;        ncol = QKVC; }
    else if (j < 1280) { src = gf; jj = j - 768;  ncol = HC;   }
    else if (j < 2048) { src = wq; jj = j - 1280; ncol = QKVC; }
    else               { src = wf; jj = j - 2048; ncol = HC;   }
    d_wh[idx] = __float2half_rn(src[(size_t)c * ncol + jj]);
}

// ============ WMMA fp16 GEMM: d_big = A @ W (fp32 accum, fp16 out) =========
// 256-thread CTA, BM=128, BN=128, BK=32; warp tile 64x32 (2x4 warp grid).
// __launch_bounds__(256, 2): 2 CTAs/SM -> 50% occupancy (R14 profile showed
// 512thr/128reg = whole RF = 1 CTA/SM = occ 24.5% was the binder).
#define BKT 32
#define LDAs 136
#define ASTG (BKT * LDAs)       // 4352 halves per matrix per stage
#define STGE (2 * ASTG)         // A + B
#define NSTG 3
#define GEMM_SMEM (NSTG * STGE * 2)   // 52224 B

__global__ __launch_bounds__(256, 2) void gemm_f16()
{
    extern __shared__ __half sm[];
    const uint32_t smb = smem_u32(sm);
    const int t   = threadIdx.x;
    const int wid = t >> 5;

    const int nt = blockIdx.x;          // 0..19
    const int mt = blockIdx.y;          // 0..1023
    const int j0 = nt * 128;
    const int r0 = mt * 128;
    const int b  = mt >> 7;
    const int n0 = r0 & (NN - 1);

    const __half* ax = d_xh + (size_t)b * CC * NN + n0;
    const __half* bw = d_wh + j0;

    const int wm = (wid & 1) * 64;      // 2 warp rows (M)
    const int wn = (wid >> 1) * 32;     // 4 warp cols (N)

    wmma::fragment<wmma::accumulator, 16, 16, 16, float> acc[4][2];
#pragma unroll
    for (int i = 0; i < 4; i++)
#pragma unroll
        for (int j = 0; j < 2; j++) wmma::fill_fragment(acc[i][j], 0.0f);

    // stage loader: A 512 + B 512 chunks of 16B; 256 thr x 4
    auto load_stage = [&](int s, int c0) {
        const uint32_t sbase = smb + (uint32_t)(s * STGE) * 2;
#pragma unroll
        for (int i = 0; i < 4; i++) {
            int q = t + i * 256;
            if (q < 512) {
                int k = q >> 4, c8 = (q & 15) << 3;
                cp16(sbase + (uint32_t)(k * LDAs + c8) * 2,
                     ax + (size_t)(c0 + k) * NN + c8);
            } else {
                int q2 = q - 512;
                int k = q2 >> 4, j8 = (q2 & 15) << 3;
                cp16(sbase + (uint32_t)(ASTG + k * LDAs + j8) * 2,
                     bw + (size_t)(c0 + k) * OSTR + j8);
            }
        }
        asm volatile("cp.async.commit_group;");
    };

    load_stage(0, 0);
    load_stage(1, BKT);

#pragma unroll 1
    for (int kt = 0; kt < 8; kt++) {
        if (kt + 2 < 8) {
            load_stage((kt + 2) % 3, (kt + 2) * BKT);
            asm volatile("cp.async.wait_group 2;");
        } else if (kt + 1 < 8) {
            asm volatile("cp.async.wait_group 1;");
        } else {
            asm volatile("cp.async.wait_group 0;");
        }
        __syncthreads();

        const __half* st = sm + (size_t)(kt % 3) * STGE;
        const __half* As = st;
        const __half* Bs = st + ASTG;

#pragma unroll
        for (int ks = 0; ks < 2; ks++) {
            wmma::fragment<wmma::matrix_a, 16, 16, 16, __half,
                           wmma::col_major> af[4];
#pragma unroll
            for (int i = 0; i < 4; i++)
                wmma::load_matrix_sync(af[i],
                    As + (ks * 16) * LDAs + wm + i * 16, LDAs);
#pragma unroll
            for (int j = 0; j < 2; j++) {
                wmma::fragment<wmma::matrix_b, 16, 16, 16, __half,
                               wmma::row_major> bf;
                wmma::load_matrix_sync(bf,
                    Bs + (ks * 16) * LDAs + wn + j * 16, LDAs);
#pragma unroll
                for (int i = 0; i < 4; i++)
                    wmma::mma_sync(acc[i][j], af[i], bf, acc[i][j]);
            }
        }
        __syncthreads();
    }

    // epilogue: convert f32 accum -> f16 accum fragment, direct store
    // (f16/f32 accumulator fragment layouts verified identical: R12 vs R13
    //  produced bit-identical rel_err through two different epilogues)
#pragma unroll
    for (int i = 0; i < 4; i++)
#pragma unroll
        for (int j = 0; j < 2; j++) {
            wmma::fragment<wmma::accumulator, 16, 16, 16, __half> ho;
#pragma unroll
            for (int e = 0; e < ho.num_elements; e++)
                ho.x[e] = __float2half_rn(acc[i][j].x[e]);
            wmma::store_matrix_sync(
                d_big + (size_t)(r0 + wm + i * 16) * OSTR + j0 + wn + j * 16,
                ho, OSTR, wmma::mem_row_major);
        }
}

// ======== fused tensor-core attention (both branches) + final blend ========
#define LDH 72
#define LDS4 68
#define A_QH   0
#define A_KH   9216
#define A_VH   18432
#define A_PH   27648
#define A_SS   36864
#define A_CG   54272
#define A_BG   71680
#define A_BW   71936
#define ATTN_SMEM 72192

__global__ __launch_bounds__(256) void attn_combine(
    const float* __restrict__ x, float* __restrict__ out)
{
    extern __shared__ char smem[];
    __half* Qh = (__half*)(smem + A_QH);
    __half* Kh = (__half*)(smem + A_KH);
    __half* Vh = (__half*)(smem + A_VH);
    __half* Ph = (__half*)(smem + A_PH);
    float*  Ss = (float*)(smem + A_SS);
    float*  Cg = (float*)(smem + A_CG);
    float*  sbg = (float*)(smem + A_BG);
    float*  sbw = (float*)(smem + A_BW);

    const int t    = threadIdx.x;
    const int wid  = t >> 5;
    const int bx   = blockIdx.x;
    const int win  = bx >> 2;
    const int head = bx & 3;
    const int b    = win >> 8;
    const int wib  = win & 255;
    const int xw   = wib >> 4;
    const int yw   = wib & 15;

    const int li  = t >> 2;            // token 0..63
    const int ld0 = (t & 3) << 4;      // 16 d's per thread
    const int lni = ((xw << 3) + (li >> 3)) * WW2 + (yw << 3) + (li & 7);

    if (t < 64) {
        int ni = ((xw << 3) + (t >> 3)) * WW2 + (yw << 3) + (t & 7);
        sbg[t] = d_xbit_g[(size_t)b * NN + ni];
    } else if (t < 128) {
        int tt = t - 64;
        int ni = ((xw << 3) + (tt >> 3)) * WW2 + (yw << 3) + (tt & 7);
        sbw[tt] = d_xbit_w[(size_t)b * NN + ni];
    }

    const int wi = (wid >> 1) * 16;
    const int wj = (wid & 1) * 32;
    const __half2 qscale = __half2half2(__float2half_rn(0.125f));

#pragma unroll
    for (int br = 0; br < 2; br++) {
        const int qoff = (br ? OFF_WQKV : OFF_GQKV) + head * 64;
        float* cdst = br ? Ss : Cg;

        // ---- load QKV (fp16 global -> fp16 smem) ----
        {
            const __half* rp = d_big + (size_t)(b * NN + lni) * OSTR + qoff;
#pragma unroll
            for (int u = 0; u < 2; u++) {
                int d = ld0 + u * 8;
                uint4 qv = *(const uint4*)&rp[d];
                __half2* q2 = (__half2*)&qv;
                q2[0] = __hmul2(q2[0], qscale);
                q2[1] = __hmul2(q2[1], qscale);
                q2[2] = __hmul2(q2[2], qscale);
                q2[3] = __hmul2(q2[3], qscale);
                *(uint4*)&Qh[li * LDH + d] = qv;
                *(uint4*)&Kh[li * LDH + d] = *(const uint4*)&rp[256 + d];
                *(uint4*)&Vh[li * LDH + d] = *(const uint4*)&rp[512 + d];
            }
        }
        __syncthreads();

        // ---- S = Q K^T ----
        {
            wmma::fragment<wmma::accumulator, 16, 16, 16, float> c0, c1;
            wmma::fill_fragment(c0, 0.0f);
            wmma::fill_fragment(c1, 0.0f);
#pragma unroll
            for (int k0 = 0; k0 < 64; k0 += 16) {
                wmma::fragment<wmma::matrix_a, 16, 16, 16, __half,
                               wmma::row_major> af;
                wmma::fragment<wmma::matrix_b, 16, 16, 16, __half,
                               wmma::col_major> bf0, bf1;
                wmma::load_matrix_sync(af,  Qh + wi * LDH + k0, LDH);
                wmma::load_matrix_sync(bf0, Kh + wj * LDH + k0, LDH);
                wmma::load_matrix_sync(bf1, Kh + (wj + 16) * LDH + k0, LDH);
                wmma::mma_sync(c0, af, bf0, c0);
                wmma::mma_sync(c1, af, bf1, c1);
            }
            wmma::store_matrix_sync(Ss + wi * LDS4 + wj,      c0, LDS4,
                                    wmma::mem_row_major);
            wmma::store_matrix_sync(Ss + wi * LDS4 + wj + 16, c1, LDS4,
                                    wmma::mem_row_major);
        }
        __syncthreads();

        // ---- softmax: 4 lanes per row ----
        {
            const int row = t >> 2;
            const int qq  = t & 3;
            float* sr = Ss + row * LDS4 + qq * 16;
            float4 v0 = *(float4*)&sr[0];
            float4 v1 = *(float4*)&sr[4];
            float4 v2 = *(float4*)&sr[8];
            float4 v3 = *(float4*)&sr[12];
            float m = fmaxf(fmaxf(fmaxf(v0.x, v0.y), fmaxf(v0.z, v0.w)),
                     fmaxf(fmaxf(fmaxf(v1.x, v1.y), fmaxf(v1.z, v1.w)),
                     fmaxf(fmaxf(fmaxf(v2.x, v2.y), fmaxf(v2.z, v2.w)),
                           fmaxf(fmaxf(v3.x, v3.y), fmaxf(v3.z, v3.w)))));
            m = fmaxf(m, __shfl_xor_sync(0xffffffffu, m, 1));
            m = fmaxf(m, __shfl_xor_sync(0xffffffffu, m, 2));
            float e[16];
            e[0] = __expf(v0.x - m); e[1] = __expf(v0.y - m);
            e[2] = __expf(v0.z - m); e[3] = __expf(v0.w - m);
            e[4] = __expf(v1.x - m); e[5] = __expf(v1.y - m);
            e[6] = __expf(v1.z - m); e[7] = __expf(v1.w - m);
            e[8] = __expf(v2.x - m); e[9] = __expf(v2.y - m);
            e[10] = __expf(v2.z - m); e[11] = __expf(v2.w - m);
            e[12] = __expf(v3.x - m); e[13] = __expf(v3.y - m);
            e[14] = __expf(v3.z - m); e[15] = __expf(v3.w - m);
            float sum = 0.f;
#pragma unroll
            for (int u = 0; u < 16; u++) sum += e[u];
            sum += __shfl_xor_sync(0xffffffffu, sum, 1);
            sum += __shfl_xor_sync(0xffffffffu, sum, 2);
            float inv = 1.0f / sum;
            __half* pr = Ph + row * LDH + qq * 16;
#pragma unroll
            for (int u = 0; u < 4; u++) {
                __half hp[4] = {
                    __float2half_rn(e[u * 4 + 0] * inv),
                    __float2half_rn(e[u * 4 + 1] * inv),
                    __float2half_rn(e[u * 4 + 2] * inv),
                    __float2half_rn(e[u * 4 + 3] * inv)};
                *(uint2*)&pr[u * 4] = *(uint2*)hp;
            }
        }
        __syncthreads();

        // ---- ctx = P V ----
        {
            wmma::fragment<wmma::accumulator, 16, 16, 16, float> c0, c1;
            wmma::fill_fragment(c0, 0.0f);
            wmma::fill_fragment(c1, 0.0f);
#pragma unroll
            for (int k0 = 0; k0 < 64; k0 += 16) {
                wmma::fragment<wmma::matrix_a, 16, 16, 16, __half,
                               wmma::row_major> af;
                wmma::fragment<wmma::matrix_b, 16, 16, 16, __half,
                               wmma::row_major> bf0, bf1;
                wmma::load_matrix_sync(af,  Ph + wi * LDH + k0, LDH);
                wmma::load_matrix_sync(bf0, Vh + k0 * LDH + wj, LDH);
                wmma::load_matrix_sync(bf1, Vh + k0 * LDH + wj + 16, LDH);
                wmma::mma_sync(c0, af, bf0, c0);
                wmma::mma_sync(c1, af, bf1, c1);
            }
            wmma::store_matrix_sync(cdst + wi * LDS4 + wj,      c0, LDS4,
                                    wmma::mem_row_major);
            wmma::store_matrix_sync(cdst + wi * LDS4 + wj + 16, c1, LDS4,
                                    wmma::mem_row_major);
        }
        __syncthreads();
    }

    // ---- final blend ----
    for (int e = t; e < 4096; e += 256) {
        int d  = e >> 6;
        int ii = e & 63;
        int ni = ((xw << 3) + (ii >> 3)) * WW2 + (yw << 3) + (ii & 7);
        size_t gidx = ((size_t)(b * CC + head * 64 + d)) * NN + ni;
        float vg = Cg[ii * LDS4 + d];
        float vw = Ss[ii * LDS4 + d];
        float wv = sbw[ii] * vw;
        float sg = 1.0f / (1.0f + __expf(-wv));
        out[gidx] = x[gidx] * sg + (sbg[ii] * vg) * (1.0f - sg);
    }
}

// --------- fold fc2+bit into a single 2C vector (warp per k) --------------
__global__ __launch_bounds__(256) void fuse_fw(
    const float* __restrict__ gfc2w, const float* __restrict__ gfc2b,
    const float* __restrict__ gbitw, const float* __restrict__ gbitb,
    const float* __restrict__ wfc2w, const float* __restrict__ wfc2b,
    const float* __restrict__ wbitw, const float* __restrict__ wbitb)
{
    const int sel  = blockIdx.y;
    const float* fc2w = sel ? wfc2w : gfc2w;
    const float* fc2b = sel ? wfc2b : gfc2b;
    const float* bitw = sel ? wbitw : gbitw;
    const float* bitb = sel ? wbitb : gbitb;

    const int wid  = threadIdx.x >> 5;
    const int lane = threadIdx.x & 31;
    const int k    = blockIdx.x * 8 + wid;

    float s = 0.f;
#pragma unroll
    for (int c = lane; c < CC; c += 32)
        s += fc2w[(size_t)k * CC + c] * bitw[c];
#pragma unroll
    for (int off = 16; off > 0; off >>= 1)
        s += __shfl_xor_sync(0xffffffffu, s, off);
    if (lane == 0) d_fw[sel][k] = s;

    if (blockIdx.x == 0 && wid == 0) {
        float sb = 0.f;
#pragma unroll
        for (int c = lane; c < CC; c += 32)
            sb += fc2b[c] * bitw[c];
#pragma unroll
        for (int off = 16; off > 0; off >>= 1)
            sb += __shfl_xor_sync(0xffffffffu, sb, off);
        if (lane == 0) d_fb[sel] = sb + bitb[0];
    }
}

// -------- InstanceNorm stats, vectorized: thread reads 8 halves/row --------
__global__ __launch_bounds__(256) void inorm_stats()
{
    const int b   = blockIdx.x;
    const int sel = blockIdx.y;
    const int ch0 = blockIdx.z * 256;
    const int hoff = (sel ? OFF_WH : OFF_GH) + ch0;
    const int g  = threadIdx.x & 31;    // 8-channel group
    const int rr = threadIdx.x >> 5;    // row lane

    float s[8], s2[8];
#pragma unroll
    for (int u = 0; u < 8; u++) { s[u] = 0.f; s2[u] = 0.f; }

    const __half* base = d_big + (size_t)b * NN * OSTR + hoff + g * 8;
    for (int n = rr; n < NN; n += 8) {
        uint4 pk = *(const uint4*)&base[(size_t)n * OSTR];
        __half2* h2 = (__half2*)&pk;
#pragma unroll
        for (int u = 0; u < 4; u++) {
            float2 f = __half22float2(h2[u]);
            s[2 * u]      += f.x; s2[2 * u]      += f.x * f.x;
            s[2 * u + 1]  += f.y; s2[2 * u + 1]  += f.y * f.y;
        }
    }

    __shared__ float ss[8][256], ss2[8][256];
#pragma unroll
    for (int u = 0; u < 8; u++) {
        ss[rr][g * 8 + u]  = s[u];
        ss2[rr][g * 8 + u] = s2[u];
    }
    __syncthreads();

    const int c = threadIdx.x;
    float a = 0.f, a2 = 0.f;
#pragma unroll
    for (int r = 0; r < 8; r++) { a += ss[r][c]; a2 += ss2[r][c]; }
    float m   = a * (1.0f / NN);
    float var = a2 * (1.0f / NN) - m * m;
    d_mu[sel][b * HC + ch0 + c]   = m;
    d_rstd[sel][b * HC + ch0 + c] = rsqrtf(var + 1e-5f);
}

// ---------------- norm + gelu + fused fc2/bit GEMV -> x_bit ----------------
__global__ __launch_bounds__(256) void mlp_bit()
{
    const int sel  = blockIdx.y;
    const int hoff = sel ? OFF_WH : OFF_GH;
    float* xbit    = sel ? d_xbit_w : d_xbit_g;

    __shared__ float smu[HC], srs[HC], sfw[HC];
    const int t  = threadIdx.x;
    const int r0 = blockIdx.x * 8;
    const int b  = r0 >> 14;

    smu[t]       = d_mu[sel][b * HC + t];
    smu[t + 256] = d_mu[sel][b * HC + t + 256];
    srs[t]       = d_rstd[sel][b * HC + t];
    srs[t + 256] = d_rstd[sel][b * HC + t + 256];
    sfw[t]       = d_fw[sel][t];
    sfw[t + 256] = d_fw[sel][t + 256];
    __syncthreads();

    const float fb = d_fb[sel];
    const int w = t >> 5, lane = t & 31;
    const int r = r0 + w;
    const __half* hr = d_big + (size_t)r * OSTR + hoff;

    float acc = 0.f;
#pragma unroll
    for (int ii = 0; ii < 8; ii++) {
        int k = (lane + (ii << 5)) * 2;
        __half2 hv = *(const __half2*)&hr[k];
        float2 vf = __half22float2(hv);
        float v0 = (vf.x - smu[k]) * srs[k];
        float v1 = (vf.y - smu[k + 1]) * srs[k + 1];
        float g0 = 0.5f * v0 * (1.0f + erff(v0 * 0.70710678118f));
        float g1 = 0.5f * v1 * (1.0f + erff(v1 * 0.70710678118f));
        acc += g0 * sfw[k] + g1 * sfw[k + 1];
    }
#pragma unroll
    for (int off = 16; off > 0; off >>= 1)
        acc += __shfl_xor_sync(0xffffffffu, acc, off);
    if (lane == 0) xbit[r] = fmaxf(acc + fb, 0.0f);
}

// ---------------- launch ----------------
extern "C" void kernel_launch(void* const* d_in, const int* in_sizes, int n_in,
                              void* d_out, int out_size)
{
    const float* x       = (const float*)d_in[0];
    const float* g_qkv   = (const float*)d_in[1];
    const float* g_fc1_w = (const float*)d_in[2];
    const float* g_fc2_w = (const float*)d_in[4];
    const float* g_fc2_b = (const float*)d_in[5];
    const float* g_bit_w = (const float*)d_in[6];
    const float* g_bit_b = (const float*)d_in[7];
    const float* w_qkv   = (const float*)d_in[8];
    const float* w_fc1_w = (const float*)d_in[9];
    const float* w_fc2_w = (const float*)d_in[11];
    const float* w_fc2_b = (const float*)d_in[12];
    const float* w_bit_w = (const float*)d_in[13];
    const float* w_bit_b = (const float*)d_in[14];
    float* out = (float*)d_out;

    cudaFuncSetAttribute(gemm_f16, cudaFuncAttributeMaxDynamicSharedMemorySize,
                         GEMM_SMEM);
    cudaFuncSetAttribute(attn_combine, cudaFuncAttributeMaxDynamicSharedMemorySize,
                         ATTN_SMEM);

    // prep (gemm stays launch #4 -> lands in the ncu capture window)
    split_x<<<((size_t)BB * CC * NN / 4) / 256, 256>>>(x);
    pack_w<<<(CC * OSTR) / 256, 256>>>(g_qkv, g_fc1_w, w_qkv, w_fc1_w);
    fuse_fw<<<dim3(HC / 8, 2), 256>>>(g_fc2_w, g_fc2_b, g_bit_w, g_bit_b,
                                      w_fc2_w, w_fc2_b, w_bit_w, w_bit_b);

    // one fused tensor-core GEMM (fp32 accum, 2 CTAs/SM): [BN,256]@[256,2560]
    gemm_f16<<<dim3(OSTR / 128, BN / 128), 256, GEMM_SMEM>>>();

    // bit branch (attn_combine consumes x_bit)
    inorm_stats<<<dim3(BB, 2, 2), 256>>>();
    mlp_bit<<<dim3(BN / 8, 2), 256>>>();

    // fused tensor-core attention (both branches) + final blend
    attn_combine<<<8192, 256, ATTN_SMEM>>>(x, out);
}

// round 17
// speedup vs baseline: 1.6184x; 1.4114x over previous
#include <cuda_runtime.h>
#include <cuda_fp16.h>
#include <cuda_bf16.h>
#include <mma.h>
#include <cstddef>
#include <cstdint>
#include <math.h>

using namespace nvcuda;

// Problem constants
#define BB 8
#define CC 256
#define HH 128
#define WW2 128
#define NN 16384           // H*W
#define BN 131072          // B*N
#define QKVC 768           // 3C
#define HC 512             // 2C
#define OSTR 2560          // fused GEMM output columns

// column offsets inside the fused output  [gqkv 0..768 | gh 768..1280 | wqkv 1280..2048 | wh 2048..2560]
#define OFF_GQKV 0
#define OFF_GH   768
#define OFF_WQKV 1280
#define OFF_WH   2048

// ---------------- scratch (device globals; no allocation) ----------------
__device__ __half d_big[(size_t)BN * OSTR];  // fused GEMM output, fp16 (670 MB)
__device__ __half d_xh[(size_t)BB * CC * NN];
__device__ __half d_wh[(size_t)CC * OSTR];
__device__ float d_xbit_g[BN];
__device__ float d_xbit_w[BN];
__device__ float d_sum[2][BB * HC];    // per (b, channel) sums (atomics)
__device__ float d_ssq[2][BB * HC];    // per (b, channel) sum of squares
__device__ float d_fw[2][HC];
__device__ float d_fb[2];

// ======================= helpers ============================
__device__ __forceinline__ uint32_t smem_u32(const void* p) {
    uint32_t a;
    asm("{ .reg .u64 t; cvta.to.shared.u64 t, %1; cvt.u32.u64 %0, t; }"
        : "=r"(a) : "l"(p));
    return a;
}
__device__ __forceinline__ void cp16(uint32_t dst, const void* src) {
    asm volatile("cp.async.cg.shared.global [%0], [%1], 16;"
                 :: "r"(dst), "l"(src));
}

// ================== convert x -> fp16, same layout ==================
__global__ __launch_bounds__(256) void split_x(const float* __restrict__ x)
{
    size_t i = ((size_t)blockIdx.x * 256 + threadIdx.x) * 4;
    float4 v = *(const float4*)&x[i];
    __half h[4];
    h[0] = __float2half_rn(v.x);
    h[1] = __float2half_rn(v.y);
    h[2] = __float2half_rn(v.z);
    h[3] = __float2half_rn(v.w);
    *(uint2*)&d_xh[i] = *(uint2*)h;
}

// ====== pack weights into [c][2560] fp16 (fused column space) ========
__global__ __launch_bounds__(256) void pack_w(
    const float* __restrict__ gq, const float* __restrict__ gf,
    const float* __restrict__ wq, const float* __restrict__ wf)
{
    int idx = blockIdx.x * 256 + threadIdx.x;   // 0 .. CC*OSTR-1
    int c = idx / OSTR;
    int j = idx % OSTR;
    const float* src; int jj; int ncol;
    if (j < 768)       { src = gq; jj = j;        ncol = QKVC; }
    else if (j < 1280) { src = gf; jj = j - 768;  ncol = HC;   }
    else if (j < 2048) { src = wq; jj = j - 1280; ncol = QKVC; }
    else               { src = wf; jj = j - 2048; ncol = HC;   }
    d_wh[idx] = __float2half_rn(src[(size_t)c * ncol + jj]);
}

// -------- zero the stat accumulators (atomics target) --------
__global__ __launch_bounds__(256) void zero_stats()
{
    int i = blockIdx.x * 256 + threadIdx.x;     // 0 .. 2*BB*HC-1
    ((float*)d_sum)[i] = 0.0f;
    ((float*)d_ssq)[i] = 0.0f;
}

// ============ WMMA fp16 GEMM: d_big = A @ W (fp32 accum, fp16 out) =========
// 256-thread CTA, BM=128, BN=128, BK=32; warp tile 64x32 (2x4 warp grid).
// NSTG=4 + single __syncthreads per K-iter (loads issued AFTER the barrier:
// a warp one iter ahead writes stage (kt+4)&3 == kt&3 only after the barrier
// that proves all warps finished reading stage kt -> no hazard).
// Epilogue: h-tiles also land in smem; block reduces column sums/sumsqs and
// atomicAdds into d_sum/d_ssq -> the separate inorm_stats pass is deleted.
#define BKT 32
#define LDAs 136
#define ASTG (BKT * LDAs)       // 4352 halves per matrix per stage
#define STGE (2 * ASTG)         // A + B = 8704 halves
#define NSTG 4
#define GEMM_SMEM (NSTG * STGE * 2)   // 69632 B

__global__ __launch_bounds__(256, 2) void gemm_f16()
{
    extern __shared__ __half sm[];
    const uint32_t smb = smem_u32(sm);
    const int t   = threadIdx.x;
    const int wid = t >> 5;

    const int nt = blockIdx.x;          // 0..19
    const int mt = blockIdx.y;          // 0..1023
    const int j0 = nt * 128;
    const int r0 = mt * 128;
    const int b  = mt >> 7;
    const int n0 = r0 & (NN - 1);

    const __half* ax = d_xh + (size_t)b * CC * NN + n0;
    const __half* bw = d_wh + j0;

    const int wm = (wid & 1) * 64;      // 2 warp rows (M)
    const int wn = (wid >> 1) * 32;     // 4 warp cols (N)

    wmma::fragment<wmma::accumulator, 16, 16, 16, float> acc[4][2];
#pragma unroll
    for (int i = 0; i < 4; i++)
#pragma unroll
        for (int j = 0; j < 2; j++) wmma::fill_fragment(acc[i][j], 0.0f);

    // stage loader: A 512 + B 512 chunks of 16B; 256 thr x 4
    auto load_stage = [&](int s, int c0) {
        const uint32_t sbase = smb + (uint32_t)(s * STGE) * 2;
#pragma unroll
        for (int i = 0; i < 4; i++) {
            int q = t + i * 256;
            if (q < 512) {
                int k = q >> 4, c8 = (q & 15) << 3;
                cp16(sbase + (uint32_t)(k * LDAs + c8) * 2,
                     ax + (size_t)(c0 + k) * NN + c8);
            } else {
                int q2 = q - 512;
                int k = q2 >> 4, j8 = (q2 & 15) << 3;
                cp16(sbase + (uint32_t)(ASTG + k * LDAs + j8) * 2,
                     bw + (size_t)(c0 + k) * OSTR + j8);
            }
        }
        asm volatile("cp.async.commit_group;");
    };

    load_stage(0, 0);
    load_stage(1, BKT);
    load_stage(2, 2 * BKT);

#pragma unroll 1
    for (int kt = 0; kt < 8; kt++) {
        // ensure group kt complete: after prologue+issues, newest groups are
        // kt+1, kt+2 (and kt+3 not yet issued this iter)
        if (kt <= 5)      asm volatile("cp.async.wait_group 2;");
        else if (kt == 6) asm volatile("cp.async.wait_group 1;");
        else              asm volatile("cp.async.wait_group 0;");
        __syncthreads();                 // single barrier per iteration

        if (kt + 3 < 8) load_stage((kt + 3) & 3, (kt + 3) * BKT);

        const __half* st = sm + (size_t)(kt & 3) * STGE;
        const __half* As = st;
        const __half* Bs = st + ASTG;

#pragma unroll
        for (int ks = 0; ks < 2; ks++) {
            wmma::fragment<wmma::matrix_a, 16, 16, 16, __half,
                           wmma::col_major> af[4];
#pragma unroll
            for (int i = 0; i < 4; i++)
                wmma::load_matrix_sync(af[i],
                    As + (ks * 16) * LDAs + wm + i * 16, LDAs);
#pragma unroll
            for (int j = 0; j < 2; j++) {
                wmma::fragment<wmma::matrix_b, 16, 16, 16, __half,
                               wmma::row_major> bf;
                wmma::load_matrix_sync(bf,
                    Bs + (ks * 16) * LDAs + wn + j * 16, LDAs);
#pragma unroll
                for (int i = 0; i < 4; i++)
                    wmma::mma_sync(acc[i][j], af[i], bf, acc[i][j]);
            }
        }
    }
    __syncthreads();    // all reads of smem stages done before epilogue reuse

    // is this an h-region N-tile?  g_h: nt 6..9, w_h: nt 16..19
    const bool is_h = (nt >= 6 && nt < 10) || (nt >= 16);

    // epilogue: f32 accum -> f16 fragment -> global (and smem copy for stats)
#pragma unroll
    for (int i = 0; i < 4; i++)
#pragma unroll
        for (int j = 0; j < 2; j++) {
            wmma::fragment<wmma::accumulator, 16, 16, 16, __half> ho;
#pragma unroll
            for (int e = 0; e < ho.num_elements; e++)
                ho.x[e] = __float2half_rn(acc[i][j].x[e]);
            wmma::store_matrix_sync(
                d_big + (size_t)(r0 + wm + i * 16) * OSTR + j0 + wn + j * 16,
                ho, OSTR, wmma::mem_row_major);
            if (is_h)
                wmma::store_matrix_sync(
                    sm + (size_t)(wm + i * 16) * LDAs + wn + j * 16,
                    ho, LDAs, wmma::mem_row_major);
        }

    if (is_h) {
        __syncthreads();
        const int sel = (nt >= 16) ? 1 : 0;
        const int ch0 = (sel ? (nt - 16) : (nt - 6)) * 128;
        const int c  = t & 127;
        const int hf = t >> 7;
        float s = 0.f, q = 0.f;
#pragma unroll 4
        for (int r = hf * 64; r < hf * 64 + 64; r++) {
            float v = __half2float(sm[(size_t)r * LDAs + c]);
            s += v; q += v * v;
        }
        float* ps = (float*)(sm + 128 * LDAs + 64);   // scratch after tile
        ps[t]       = s;
        ps[256 + t] = q;
        __syncthreads();
        if (t < 128) {
            float S = ps[t] + ps[t + 128];
            float Q = ps[256 + t] + ps[256 + t + 128];
            atomicAdd(&d_sum[sel][b * HC + ch0 + t], S);
            atomicAdd(&d_ssq[sel][b * HC + ch0 + t], Q);
        }
    }
}

// ======== fused tensor-core attention (both branches) + final blend ========
#define LDH 72
#define LDS4 68
#define A_QH   0
#define A_KH   9216
#define A_VH   18432
#define A_PH   27648
#define A_SS   36864
#define A_CG   54272
#define A_BG   71680
#define A_BW   71936
#define ATTN_SMEM 72192

__global__ __launch_bounds__(256) void attn_combine(
    const float* __restrict__ x, float* __restrict__ out)
{
    extern __shared__ char smem[];
    __half* Qh = (__half*)(smem + A_QH);
    __half* Kh = (__half*)(smem + A_KH);
    __half* Vh = (__half*)(smem + A_VH);
    __half* Ph = (__half*)(smem + A_PH);
    float*  Ss = (float*)(smem + A_SS);
    float*  Cg = (float*)(smem + A_CG);
    float*  sbg = (float*)(smem + A_BG);
    float*  sbw = (float*)(smem + A_BW);

    const int t    = threadIdx.x;
    const int wid  = t >> 5;
    const int bx   = blockIdx.x;
    const int win  = bx >> 2;
    const int head = bx & 3;
    const int b    = win >> 8;
    const int wib  = win & 255;
    const int xw   = wib >> 4;
    const int yw   = wib & 15;

    const int li  = t >> 2;            // token 0..63
    const int ld0 = (t & 3) << 4;      // 16 d's per thread
    const int lni = ((xw << 3) + (li >> 3)) * WW2 + (yw << 3) + (li & 7);

    if (t < 64) {
        int ni = ((xw << 3) + (t >> 3)) * WW2 + (yw << 3) + (t & 7);
        sbg[t] = d_xbit_g[(size_t)b * NN + ni];
    } else if (t < 128) {
        int tt = t - 64;
        int ni = ((xw << 3) + (tt >> 3)) * WW2 + (yw << 3) + (tt & 7);
        sbw[tt] = d_xbit_w[(size_t)b * NN + ni];
    }

    const int wi = (wid >> 1) * 16;
    const int wj = (wid & 1) * 32;
    const __half2 qscale = __half2half2(__float2half_rn(0.125f));

#pragma unroll
    for (int br = 0; br < 2; br++) {
        const int qoff = (br ? OFF_WQKV : OFF_GQKV) + head * 64;
        float* cdst = br ? Ss : Cg;

        // ---- load QKV (fp16 global -> fp16 smem) ----
        {
            const __half* rp = d_big + (size_t)(b * NN + lni) * OSTR + qoff;
#pragma unroll
            for (int u = 0; u < 2; u++) {
                int d = ld0 + u * 8;
                uint4 qv = *(const uint4*)&rp[d];
                __half2* q2 = (__half2*)&qv;
                q2[0] = __hmul2(q2[0], qscale);
                q2[1] = __hmul2(q2[1], qscale);
                q2[2] = __hmul2(q2[2], qscale);
                q2[3] = __hmul2(q2[3], qscale);
                *(uint4*)&Qh[li * LDH + d] = qv;
                *(uint4*)&Kh[li * LDH + d] = *(const uint4*)&rp[256 + d];
                *(uint4*)&Vh[li * LDH + d] = *(const uint4*)&rp[512 + d];
            }
        }
        __syncthreads();

        // ---- S = Q K^T ----
        {
            wmma::fragment<wmma::accumulator, 16, 16, 16, float> c0, c1;
            wmma::fill_fragment(c0, 0.0f);
            wmma::fill_fragment(c1, 0.0f);
#pragma unroll
            for (int k0 = 0; k0 < 64; k0 += 16) {
                wmma::fragment<wmma::matrix_a, 16, 16, 16, __half,
                               wmma::row_major> af;
                wmma::fragment<wmma::matrix_b, 16, 16, 16, __half,
                               wmma::col_major> bf0, bf1;
                wmma::load_matrix_sync(af,  Qh + wi * LDH + k0, LDH);
                wmma::load_matrix_sync(bf0, Kh + wj * LDH + k0, LDH);
                wmma::load_matrix_sync(bf1, Kh + (wj + 16) * LDH + k0, LDH);
                wmma::mma_sync(c0, af, bf0, c0);
                wmma::mma_sync(c1, af, bf1, c1);
            }
            wmma::store_matrix_sync(Ss + wi * LDS4 + wj,      c0, LDS4,
                                    wmma::mem_row_major);
            wmma::store_matrix_sync(Ss + wi * LDS4 + wj + 16, c1, LDS4,
                                    wmma::mem_row_major);
        }
        __syncthreads();

        // ---- softmax: 4 lanes per row ----
        {
            const int row = t >> 2;
            const int qq  = t & 3;
            float* sr = Ss + row * LDS4 + qq * 16;
            float4 v0 = *(float4*)&sr[0];
            float4 v1 = *(float4*)&sr[4];
            float4 v2 = *(float4*)&sr[8];
            float4 v3 = *(float4*)&sr[12];
            float m = fmaxf(fmaxf(fmaxf(v0.x, v0.y), fmaxf(v0.z, v0.w)),
                     fmaxf(fmaxf(fmaxf(v1.x, v1.y), fmaxf(v1.z, v1.w)),
                     fmaxf(fmaxf(fmaxf(v2.x, v2.y), fmaxf(v2.z, v2.w)),
                           fmaxf(fmaxf(v3.x, v3.y), fmaxf(v3.z, v3.w)))));
            m = fmaxf(m, __shfl_xor_sync(0xffffffffu, m, 1));
            m = fmaxf(m, __shfl_xor_sync(0xffffffffu, m, 2));
            float e[16];
            e[0] = __expf(v0.x - m); e[1] = __expf(v0.y - m);
            e[2] = __expf(v0.z - m); e[3] = __expf(v0.w - m);
            e[4] = __expf(v1.x - m); e[5] = __expf(v1.y - m);
            e[6] = __expf(v1.z - m); e[7] = __expf(v1.w - m);
            e[8] = __expf(v2.x - m); e[9] = __expf(v2.y - m);
            e[10] = __expf(v2.z - m); e[11] = __expf(v2.w - m);
            e[12] = __expf(v3.x - m); e[13] = __expf(v3.y - m);
            e[14] = __expf(v3.z - m); e[15] = __expf(v3.w - m);
            float sum = 0.f;
#pragma unroll
            for (int u = 0; u < 16; u++) sum += e[u];
            sum += __shfl_xor_sync(0xffffffffu, sum, 1);
            sum += __shfl_xor_sync(0xffffffffu, sum, 2);
            float inv = 1.0f / sum;
            __half* pr = Ph + row * LDH + qq * 16;
#pragma unroll
            for (int u = 0; u < 4; u++) {
                __half hp[4] = {
                    __float2half_rn(e[u * 4 + 0] * inv),
                    __float2half_rn(e[u * 4 + 1] * inv),
                    __float2half_rn(e[u * 4 + 2] * inv),
                    __float2half_rn(e[u * 4 + 3] * inv)};
                *(uint2*)&pr[u * 4] = *(uint2*)hp;
            }
        }
        __syncthreads();

        // ---- ctx = P V ----
        {
            wmma::fragment<wmma::accumulator, 16, 16, 16, float> c0, c1;
            wmma::fill_fragment(c0, 0.0f);
            wmma::fill_fragment(c1, 0.0f);
#pragma unroll
            for (int k0 = 0; k0 < 64; k0 += 16) {
                wmma::fragment<wmma::matrix_a, 16, 16, 16, __half,
                               wmma::row_major> af;
                wmma::fragment<wmma::matrix_b, 16, 16, 16, __half,
                               wmma::row_major> bf0, bf1;
                wmma::load_matrix_sync(af,  Ph + wi * LDH + k0, LDH);
                wmma::load_matrix_sync(bf0, Vh + k0 * LDH + wj, LDH);
                wmma::load_matrix_sync(bf1, Vh + k0 * LDH + wj + 16, LDH);
                wmma::mma_sync(c0, af, bf0, c0);
                wmma::mma_sync(c1, af, bf1, c1);
            }
            wmma::store_matrix_sync(cdst + wi * LDS4 + wj,      c0, LDS4,
                                    wmma::mem_row_major);
            wmma::store_matrix_sync(cdst + wi * LDS4 + wj + 16, c1, LDS4,
                                    wmma::mem_row_major);
        }
        __syncthreads();
    }

    // ---- final blend ----
    for (int e = t; e < 4096; e += 256) {
        int d  = e >> 6;
        int ii = e & 63;
        int ni = ((xw << 3) + (ii >> 3)) * WW2 + (yw << 3) + (ii & 7);
        size_t gidx = ((size_t)(b * CC + head * 64 + d)) * NN + ni;
        float vg = Cg[ii * LDS4 + d];
        float vw = Ss[ii * LDS4 + d];
        float wv = sbw[ii] * vw;
        float sg = 1.0f / (1.0f + __expf(-wv));
        out[gidx] = x[gidx] * sg + (sbg[ii] * vg) * (1.0f - sg);
    }
}

// --------- fold fc2+bit into a single 2C vector (warp per k) --------------
__global__ __launch_bounds__(256) void fuse_fw(
    const float* __restrict__ gfc2w, const float* __restrict__ gfc2b,
    const float* __restrict__ gbitw, const float* __restrict__ gbitb,
    const float* __restrict__ wfc2w, const float* __restrict__ wfc2b,
    const float* __restrict__ wbitw, const float* __restrict__ wbitb)
{
    const int sel  = blockIdx.y;
    const float* fc2w = sel ? wfc2w : gfc2w;
    const float* fc2b = sel ? wfc2b : gfc2b;
    const float* bitw = sel ? wbitw : gbitw;
    const float* bitb = sel ? wbitb : gbitb;

    const int wid  = threadIdx.x >> 5;
    const int lane = threadIdx.x & 31;
    const int k    = blockIdx.x * 8 + wid;

    float s = 0.f;
#pragma unroll
    for (int c = lane; c < CC; c += 32)
        s += fc2w[(size_t)k * CC + c] * bitw[c];
#pragma unroll
    for (int off = 16; off > 0; off >>= 1)
        s += __shfl_xor_sync(0xffffffffu, s, off);
    if (lane == 0) d_fw[sel][k] = s;

    if (blockIdx.x == 0 && wid == 0) {
        float sb = 0.f;
#pragma unroll
        for (int c = lane; c < CC; c += 32)
            sb += fc2b[c] * bitw[c];
#pragma unroll
        for (int off = 16; off > 0; off >>= 1)
            sb += __shfl_xor_sync(0xffffffffu, sb, off);
        if (lane == 0) d_fb[sel] = sb + bitb[0];
    }
}

// ---------------- norm + gelu + fused fc2/bit GEMV -> x_bit ----------------
// mu/rstd finalized here from the GEMM-accumulated sums.
__global__ __launch_bounds__(256) void mlp_bit()
{
    const int sel  = blockIdx.y;
    const int hoff = sel ? OFF_WH : OFF_GH;
    float* xbit    = sel ? d_xbit_w : d_xbit_g;

    __shared__ float smu[HC], srs[HC], sfw[HC];
    const int t  = threadIdx.x;
    const int r0 = blockIdx.x * 8;
    const int b  = r0 >> 14;

#pragma unroll
    for (int u = 0; u < 2; u++) {
        int k = t + u * 256;
        float s = d_sum[sel][b * HC + k];
        float q = d_ssq[sel][b * HC + k];
        float mu  = s * (1.0f / NN);
        float var = q * (1.0f / NN) - mu * mu;
        smu[k] = mu;
        srs[k] = rsqrtf(var + 1e-5f);
        sfw[k] = d_fw[sel][k];
    }
    __syncthreads();

    const float fb = d_fb[sel];
    const int w = t >> 5, lane = t & 31;
    const int r = r0 + w;
    const __half* hr = d_big + (size_t)r * OSTR + hoff;

    float acc = 0.f;
#pragma unroll
    for (int ii = 0; ii < 8; ii++) {
        int k = (lane + (ii << 5)) * 2;
        __half2 hv = *(const __half2*)&hr[k];
        float2 vf = __half22float2(hv);
        float v0 = (vf.x - smu[k]) * srs[k];
        float v1 = (vf.y - smu[k + 1]) * srs[k + 1];
        float g0 = 0.5f * v0 * (1.0f + erff(v0 * 0.70710678118f));
        float g1 = 0.5f * v1 * (1.0f + erff(v1 * 0.70710678118f));
        acc += g0 * sfw[k] + g1 * sfw[k + 1];
    }
#pragma unroll
    for (int off = 16; off > 0; off >>= 1)
        acc += __shfl_xor_sync(0xffffffffu, acc, off);
    if (lane == 0) xbit[r] = fmaxf(acc + fb, 0.0f);
}

// ---------------- launch ----------------
extern "C" void kernel_launch(void* const* d_in, const int* in_sizes, int n_in,
                              void* d_out, int out_size)
{
    const float* x       = (const float*)d_in[0];
    const float* g_qkv   = (const float*)d_in[1];
    const float* g_fc1_w = (const float*)d_in[2];
    const float* g_fc2_w = (const float*)d_in[4];
    const float* g_fc2_b = (const float*)d_in[5];
    const float* g_bit_w = (const float*)d_in[6];
    const float* g_bit_b = (const float*)d_in[7];
    const float* w_qkv   = (const float*)d_in[8];
    const float* w_fc1_w = (const float*)d_in[9];
    const float* w_fc2_w = (const float*)d_in[11];
    const float* w_fc2_b = (const float*)d_in[12];
    const float* w_bit_w = (const float*)d_in[13];
    const float* w_bit_b = (const float*)d_in[14];
    float* out = (float*)d_out;

    cudaFuncSetAttribute(gemm_f16, cudaFuncAttributeMaxDynamicSharedMemorySize,
                         GEMM_SMEM);
    cudaFuncSetAttribute(attn_combine, cudaFuncAttributeMaxDynamicSharedMemorySize,
                         ATTN_SMEM);

    // prep (gemm stays launch #4 -> lands in the ncu capture window)
    split_x<<<((size_t)BB * CC * NN / 4) / 256, 256>>>(x);
    pack_w<<<(CC * OSTR) / 256, 256>>>(g_qkv, g_fc1_w, w_qkv, w_fc1_w);
    zero_stats<<<(2 * BB * HC) / 256, 256>>>();

    // fused tensor-core GEMM + in-epilogue instance-norm stats
    gemm_f16<<<dim3(OSTR / 128, BN / 128), 256, GEMM_SMEM>>>();

    // bit branch (attn_combine consumes x_bit)
    fuse_fw<<<dim3(HC / 8, 2), 256>>>(g_fc2_w, g_fc2_b, g_bit_w, g_bit_b,
                                      w_fc2_w, w_fc2_b, w_bit_w, w_bit_b);
    mlp_bit<<<dim3(BN / 8, 2), 256>>>();

    // fused tensor-core attention (both branches) + final blend
    attn_combine<<<8192, 256, ATTN_SMEM>>>(x, out);
}